// round 2
// baseline (speedup 1.0000x reference)
#include <cuda_runtime.h>
#include <math.h>

#define Bc 2
#define Lc 2048
#define Dc 512
#define Vc 50257
#define NLc 12
#define Kc 5
#define Ac 128
#define Hc 128
#define Mc (Bc*Lc)      // 4096 rows
#define HALF (Dc/2)     // 256

// ---------------- scratch (device globals; no allocation allowed) ----------
__device__ float g_x  [Mc*Dc];
__device__ float g_xn [Mc*Dc];
__device__ float g_cv [Mc*Dc];
__device__ float g_mid[Mc*Dc];
__device__ float g_g1 [Mc*Dc];
__device__ float g_g2 [Mc*Dc];
__device__ float g_x2 [Mc*Dc];
__device__ float g_xr [Mc*Ac];
__device__ float g_h  [Mc*Hc];

// ---------------- embedding + RoPE ----------------
__global__ void embed_rope_k(const int* __restrict__ tokens,
                             const float* __restrict__ emb,
                             float* __restrict__ out) {
    int bl = blockIdx.x;               // 0..Mc-1
    int l  = bl & (Lc - 1);
    int tok = tokens[bl];
    const float* erow = emb + (size_t)tok * Dc;
    for (int d = threadIdx.x; d < Dc; d += blockDim.x) {
        int j = (d < HALF) ? d : d - HALF;
        double invf = exp(-((double)j / (double)HALF) * log(10000.0));
        double ang  = (double)l * invf;
        double s, c;
        sincos(ang, &s, &c);
        float v     = erow[d];
        float other = (d < HALF) ? -erow[d + HALF] : erow[d - HALF];
        out[(size_t)bl * Dc + d] = v * (float)c + other * (float)s;
    }
}

// ---------------- rmsnorm: one block per row ----------------
__global__ void rmsnorm_k(const float* __restrict__ in,
                          const float* __restrict__ w,
                          float* __restrict__ out) {
    int row = blockIdx.x;
    const float* xr = in + (size_t)row * Dc;
    float s = 0.f;
    for (int d = threadIdx.x; d < Dc; d += 256) { float v = xr[d]; s += v * v; }
    __shared__ float red[8];
    for (int o = 16; o; o >>= 1) s += __shfl_down_sync(0xffffffffu, s, o);
    if ((threadIdx.x & 31) == 0) red[threadIdx.x >> 5] = s;
    __syncthreads();
    if (threadIdx.x < 32) {
        float t = (threadIdx.x < 8) ? red[threadIdx.x] : 0.f;
        for (int o = 4; o; o >>= 1) t += __shfl_down_sync(0xffffffffu, t, o);
        if (threadIdx.x == 0) red[0] = t;
    }
    __syncthreads();
    float rinv = rsqrtf(red[0] / (float)Dc + 1e-6f);
    for (int d = threadIdx.x; d < Dc; d += 256)
        out[(size_t)row * Dc + d] = w[d] * xr[d] * rinv;
}

// ---------------- depthwise dilated conv (K=5) ----------------
__global__ void dconv_k(const float* __restrict__ xn,
                        const float* __restrict__ w,
                        const float* __restrict__ b,
                        float* __restrict__ out, int dil) {
    int idx = blockIdx.x * blockDim.x + threadIdx.x;  // < Mc*Dc
    int d  = idx & (Dc - 1);
    int bl = idx >> 9;
    int l  = bl & (Lc - 1);
    float acc = b[d];
#pragma unroll
    for (int k = 0; k < Kc; k++) {
        int ll = l + (k - 2) * dil;
        if (0 <= ll && ll < Lc)
            acc += w[d * Kc + k] * xn[(size_t)(bl + (ll - l)) * Dc + d];
    }
    out[idx] = acc;
}

// ---------------- linear recurrence: Kogge-Stone warp scan ----------------
// h_t = alpha*h_{t-1} + beta*x_t ; one warp per (batch, channel)
__global__ void recur_k(const float* __restrict__ xn,
                        const float* __restrict__ alpha,
                        const float* __restrict__ beta,
                        float* __restrict__ xr) {
    int gw   = (blockIdx.x * blockDim.x + threadIdx.x) >> 5;  // 0..255
    int lane = threadIdx.x & 31;
    int b = gw >> 7;           // / Ac
    int a = gw & (Ac - 1);
    float al = alpha[a], be = beta[a];
    float a1 = al, a2 = a1 * a1, a4 = a2 * a2, a8 = a4 * a4, a16 = a8 * a8;
    // alpha^lane by square-and-multiply
    float ap = 1.f, p = al;
    if (lane & 1)  ap *= p; p *= p;
    if (lane & 2)  ap *= p; p *= p;
    if (lane & 4)  ap *= p; p *= p;
    if (lane & 8)  ap *= p; p *= p;
    if (lane & 16) ap *= p;
    float carry = 0.f;
    const float* xbase = xn + (size_t)b * Lc * Dc + a;
    float*       obase = xr + (size_t)b * Lc * Ac + a;
    for (int seg = 0; seg < Lc / 32; seg++) {
        int t = seg * 32 + lane;
        float v = be * xbase[(size_t)t * Dc];
        float u;
        u = __shfl_up_sync(0xffffffffu, v, 1);  if (lane >= 1)  v += a1  * u;
        u = __shfl_up_sync(0xffffffffu, v, 2);  if (lane >= 2)  v += a2  * u;
        u = __shfl_up_sync(0xffffffffu, v, 4);  if (lane >= 4)  v += a4  * u;
        u = __shfl_up_sync(0xffffffffu, v, 8);  if (lane >= 8)  v += a8  * u;
        u = __shfl_up_sync(0xffffffffu, v, 16); if (lane >= 16) v += a16 * u;
        float h = v + al * ap * carry;   // + alpha^{lane+1} * carry
        obase[(size_t)t * Ac] = h;
        carry = __shfl_sync(0xffffffffu, h, 31);
    }
}

// ---------------- combine: mid += (d<A ? xr : xn) ----------------
__global__ void combine_k(const float* __restrict__ xn,
                          const float* __restrict__ xr,
                          float* __restrict__ mid) {
    int idx = blockIdx.x * blockDim.x + threadIdx.x;
    int d  = idx & (Dc - 1);
    int bl = idx >> 9;
    float add = (d < Ac) ? xr[(size_t)bl * Ac + d] : xn[idx];
    mid[idx] += add;
}

// ---------------- gate: x2 = mid + sigmoid(g1)*tanh(g2) ----------------
__global__ void gate_k(const float* __restrict__ mid,
                       const float* __restrict__ g1,
                       const float* __restrict__ g2,
                       float* __restrict__ x2) {
    int idx = blockIdx.x * blockDim.x + threadIdx.x;
    float a = g1[idx], b = g2[idx];
    float sig = 1.f / (1.f + expf(-a));
    x2[idx] = mid[idx] + sig * tanhf(b);
}

// ---------------- generic SGEMM: C = epi(A[M,K] @ W[N,K]^T) ----------------
// epi: +bias[n], optional exact GELU, optional +add0[m,n] +add1[m,n]
// block tile 128x64, K-tile 16, 256 threads, 8x4 per-thread
__global__ __launch_bounds__(256) void gemm_k(
        const float* __restrict__ A, const float* __restrict__ W,
        const float* __restrict__ bias,
        const float* __restrict__ add0, const float* __restrict__ add1,
        float* __restrict__ C, int N, int Kd, int act) {
    __shared__ float As[16][132];
    __shared__ float Bs[16][68];
    int m0 = blockIdx.y * 128;
    int n0 = blockIdx.x * 64;
    int tid = threadIdx.x;
    int tx = tid & 15, ty = tid >> 4;

    float acc[8][4];
#pragma unroll
    for (int i = 0; i < 8; i++)
#pragma unroll
        for (int j = 0; j < 4; j++) acc[i][j] = 0.f;

    int r = tid >> 2;    // 0..63
    int c = tid & 3;     // 0..3

    for (int kk = 0; kk < Kd; kk += 16) {
        // A tile: 128x16, two float4 per thread
#pragma unroll
        for (int i = 0; i < 2; i++) {
            int m = m0 + r + i * 64;
            float4 v = *(const float4*)(A + (size_t)m * Kd + kk + c * 4);
            As[c * 4 + 0][r + i * 64] = v.x;
            As[c * 4 + 1][r + i * 64] = v.y;
            As[c * 4 + 2][r + i * 64] = v.z;
            As[c * 4 + 3][r + i * 64] = v.w;
        }
        // W tile: 64x16, one float4 per thread (guard n)
        {
            int n = n0 + r;
            float4 v = make_float4(0.f, 0.f, 0.f, 0.f);
            if (n < N) v = *(const float4*)(W + (size_t)n * Kd + kk + c * 4);
            Bs[c * 4 + 0][r] = v.x;
            Bs[c * 4 + 1][r] = v.y;
            Bs[c * 4 + 2][r] = v.z;
            Bs[c * 4 + 3][r] = v.w;
        }
        __syncthreads();
#pragma unroll
        for (int k = 0; k < 16; k++) {
            float av[8], bv[4];
#pragma unroll
            for (int i = 0; i < 8; i++) av[i] = As[k][ty * 8 + i];
#pragma unroll
            for (int j = 0; j < 4; j++) bv[j] = Bs[k][tx * 4 + j];
#pragma unroll
            for (int i = 0; i < 8; i++)
#pragma unroll
                for (int j = 0; j < 4; j++) acc[i][j] += av[i] * bv[j];
        }
        __syncthreads();
    }
#pragma unroll
    for (int i = 0; i < 8; i++) {
        int m = m0 + ty * 8 + i;
#pragma unroll
        for (int j = 0; j < 4; j++) {
            int n = n0 + tx * 4 + j;
            if (n < N) {
                float v = acc[i][j];
                if (bias) v += bias[n];
                if (act)  v = 0.5f * v * (1.f + erff(v * 0.70710678118654752f));
                size_t o = (size_t)m * N + n;
                if (add0) v += add0[o];
                if (add1) v += add1[o];
                C[o] = v;
            }
        }
    }
}

// ---------------- host launcher ----------------
extern "C" void kernel_launch(void* const* d_in, const int* in_sizes, int n_in,
                              void* d_out, int out_size) {
    const int*   tokens  = (const int*)  d_in[0];
    const float* emb     = (const float*)d_in[1];
    const float* norm_w  = (const float*)d_in[2];
    const float* dconv_w = (const float*)d_in[3];
    const float* dconv_b = (const float*)d_in[4];
    const float* pconv_w = (const float*)d_in[5];
    const float* pconv_b = (const float*)d_in[6];
    const float* alpha   = (const float*)d_in[7];
    const float* beta    = (const float*)d_in[8];
    const float* w1      = (const float*)d_in[9];
    const float* b1      = (const float*)d_in[10];
    const float* w2      = (const float*)d_in[11];
    const float* b2      = (const float*)d_in[12];
    const float* down_w  = (const float*)d_in[13];
    const float* down_b  = (const float*)d_in[14];
    const float* up_w    = (const float*)d_in[15];
    const float* up_b    = (const float*)d_in[16];
    const float* fnw     = (const float*)d_in[17];
    float* out = (float*)d_out;

    float *px, *pxn, *pcv, *pmid, *pg1, *pg2, *px2, *pxr, *ph;
    cudaGetSymbolAddress((void**)&px,   g_x);
    cudaGetSymbolAddress((void**)&pxn,  g_xn);
    cudaGetSymbolAddress((void**)&pcv,  g_cv);
    cudaGetSymbolAddress((void**)&pmid, g_mid);
    cudaGetSymbolAddress((void**)&pg1,  g_g1);
    cudaGetSymbolAddress((void**)&pg2,  g_g2);
    cudaGetSymbolAddress((void**)&px2,  g_x2);
    cudaGetSymbolAddress((void**)&pxr,  g_xr);
    cudaGetSymbolAddress((void**)&ph,   g_h);

    const int EW_BLOCKS = (Mc * Dc) / 256;
    dim3 gD(Dc / 64, Mc / 128);        // N=512 GEMMs
    dim3 gH(Hc / 64, Mc / 128);        // N=128 GEMM (down)
    dim3 gV((Vc + 63) / 64, Mc / 128); // logits

    embed_rope_k<<<Mc, 256>>>(tokens, emb, px);

    for (int i = 0; i < NLc; i++) {
        int dil = 1 << (i % 3);
        rmsnorm_k<<<Mc, 256>>>(px, norm_w + i * Dc, pxn);
        dconv_k<<<EW_BLOCKS, 256>>>(pxn, dconv_w + (size_t)i * Dc * Kc,
                                    dconv_b + i * Dc, pcv, dil);
        gemm_k<<<gD, 256>>>(pcv, pconv_w + (size_t)i * Dc * Dc,
                            pconv_b + i * Dc, nullptr, nullptr, pmid, Dc, Dc, 0);
        recur_k<<<32, 256>>>(pxn, alpha + i * Ac, beta + i * Ac, pxr);
        combine_k<<<EW_BLOCKS, 256>>>(pxn, pxr, pmid);
        gemm_k<<<gD, 256>>>(pmid, w1 + (size_t)i * Dc * Dc, b1 + i * Dc,
                            nullptr, nullptr, pg1, Dc, Dc, 0);
        gemm_k<<<gD, 256>>>(pmid, w2 + (size_t)i * Dc * Dc, b2 + i * Dc,
                            nullptr, nullptr, pg2, Dc, Dc, 0);
        gate_k<<<EW_BLOCKS, 256>>>(pmid, pg1, pg2, px2);
        gemm_k<<<gH, 256>>>(px2, down_w + (size_t)i * Hc * Dc, down_b + i * Hc,
                            nullptr, nullptr, ph, Hc, Dc, 1);
        // x_new = up(hdn) + up_b + x2 + x_old   (residual folded into epilogue)
        gemm_k<<<gD, 256>>>(ph, up_w + (size_t)i * Dc * Hc, up_b + i * Dc,
                            px2, px, px, Dc, Hc, 0);
    }

    rmsnorm_k<<<Mc, 256>>>(px, fnw, pxn);
    gemm_k<<<gV, 256>>>(pxn, emb, nullptr, nullptr, nullptr, out, Vc, Dc, 0);
}

// round 3
// speedup vs baseline: 1.1072x; 1.1072x over previous
#include <cuda_runtime.h>
#include <math.h>
#include <stdint.h>

#define Bc 2
#define Lc 2048
#define Dc 512
#define Vc 50257
#define NLc 12
#define Kc 5
#define Ac 128
#define Hc 128
#define Mc (Bc*Lc)      // 4096 rows
#define HALF (Dc/2)     // 256

// ---------------- scratch (device globals; no allocation allowed) ----------
__device__ float g_x  [Mc*Dc];
__device__ float g_xn [Mc*Dc];
__device__ float g_cv [Mc*Dc];
__device__ float g_mid[Mc*Dc];
__device__ float g_g1 [Mc*Dc];
__device__ float g_g2 [Mc*Dc];
__device__ float g_x2 [Mc*Dc];
__device__ float g_xr [Mc*Ac];
__device__ float g_h  [Mc*Hc];

// ---------------- embedding + RoPE ----------------
__global__ void embed_rope_k(const int* __restrict__ tokens,
                             const float* __restrict__ emb,
                             float* __restrict__ out) {
    int bl = blockIdx.x;               // 0..Mc-1
    int l  = bl & (Lc - 1);
    int tok = tokens[bl];
    const float* erow = emb + (size_t)tok * Dc;
    for (int d = threadIdx.x; d < Dc; d += blockDim.x) {
        int j = (d < HALF) ? d : d - HALF;
        double invf = exp(-((double)j / (double)HALF) * log(10000.0));
        double ang  = (double)l * invf;
        double s, c;
        sincos(ang, &s, &c);
        float v     = erow[d];
        float other = (d < HALF) ? -erow[d + HALF] : erow[d - HALF];
        out[(size_t)bl * Dc + d] = v * (float)c + other * (float)s;
    }
}

// ---------------- rmsnorm: one block per row ----------------
__global__ void rmsnorm_k(const float* __restrict__ in,
                          const float* __restrict__ w,
                          float* __restrict__ out) {
    int row = blockIdx.x;
    const float* xr = in + (size_t)row * Dc;
    float s = 0.f;
    for (int d = threadIdx.x; d < Dc; d += 256) { float v = xr[d]; s += v * v; }
    __shared__ float red[8];
    for (int o = 16; o; o >>= 1) s += __shfl_down_sync(0xffffffffu, s, o);
    if ((threadIdx.x & 31) == 0) red[threadIdx.x >> 5] = s;
    __syncthreads();
    if (threadIdx.x < 32) {
        float t = (threadIdx.x < 8) ? red[threadIdx.x] : 0.f;
        for (int o = 4; o; o >>= 1) t += __shfl_down_sync(0xffffffffu, t, o);
        if (threadIdx.x == 0) red[0] = t;
    }
    __syncthreads();
    float rinv = rsqrtf(red[0] / (float)Dc + 1e-6f);
    for (int d = threadIdx.x; d < Dc; d += 256)
        out[(size_t)row * Dc + d] = w[d] * xr[d] * rinv;
}

// ---------------- depthwise dilated conv (K=5) ----------------
__global__ void dconv_k(const float* __restrict__ xn,
                        const float* __restrict__ w,
                        const float* __restrict__ b,
                        float* __restrict__ out, int dil) {
    int idx = blockIdx.x * blockDim.x + threadIdx.x;  // < Mc*Dc
    int d  = idx & (Dc - 1);
    int bl = idx >> 9;
    int l  = bl & (Lc - 1);
    float acc = b[d];
#pragma unroll
    for (int k = 0; k < Kc; k++) {
        int ll = l + (k - 2) * dil;
        if (0 <= ll && ll < Lc)
            acc += w[d * Kc + k] * xn[(size_t)(bl + (ll - l)) * Dc + d];
    }
    out[idx] = acc;
}

// ---------------- linear recurrence: Kogge-Stone warp scan ----------------
__global__ void recur_k(const float* __restrict__ xn,
                        const float* __restrict__ alpha,
                        const float* __restrict__ beta,
                        float* __restrict__ xr) {
    int gw   = (blockIdx.x * blockDim.x + threadIdx.x) >> 5;  // 0..255
    int lane = threadIdx.x & 31;
    int b = gw >> 7;           // / Ac
    int a = gw & (Ac - 1);
    float al = alpha[a], be = beta[a];
    float a1 = al, a2 = a1 * a1, a4 = a2 * a2, a8 = a4 * a4, a16 = a8 * a8;
    float ap = 1.f, p = al;
    if (lane & 1)  ap *= p; p *= p;
    if (lane & 2)  ap *= p; p *= p;
    if (lane & 4)  ap *= p; p *= p;
    if (lane & 8)  ap *= p; p *= p;
    if (lane & 16) ap *= p;
    float carry = 0.f;
    const float* xbase = xn + (size_t)b * Lc * Dc + a;
    float*       obase = xr + (size_t)b * Lc * Ac + a;
    for (int seg = 0; seg < Lc / 32; seg++) {
        int t = seg * 32 + lane;
        float v = be * xbase[(size_t)t * Dc];
        float u;
        u = __shfl_up_sync(0xffffffffu, v, 1);  if (lane >= 1)  v += a1  * u;
        u = __shfl_up_sync(0xffffffffu, v, 2);  if (lane >= 2)  v += a2  * u;
        u = __shfl_up_sync(0xffffffffu, v, 4);  if (lane >= 4)  v += a4  * u;
        u = __shfl_up_sync(0xffffffffu, v, 8);  if (lane >= 8)  v += a8  * u;
        u = __shfl_up_sync(0xffffffffu, v, 16); if (lane >= 16) v += a16 * u;
        float h = v + al * ap * carry;
        obase[(size_t)t * Ac] = h;
        carry = __shfl_sync(0xffffffffu, h, 31);
    }
}

// ---------------- combine: mid += (d<A ? xr : xn) ----------------
__global__ void combine_k(const float* __restrict__ xn,
                          const float* __restrict__ xr,
                          float* __restrict__ mid) {
    int idx = blockIdx.x * blockDim.x + threadIdx.x;
    int d  = idx & (Dc - 1);
    int bl = idx >> 9;
    float add = (d < Ac) ? xr[(size_t)bl * Ac + d] : xn[idx];
    mid[idx] += add;
}

// ---------------- gate: x2 = mid + sigmoid(g1)*tanh(g2) ----------------
__global__ void gate_k(const float* __restrict__ mid,
                       const float* __restrict__ g1,
                       const float* __restrict__ g2,
                       float* __restrict__ x2) {
    int idx = blockIdx.x * blockDim.x + threadIdx.x;
    float a = g1[idx], b = g2[idx];
    float sig = 1.f / (1.f + expf(-a));
    x2[idx] = mid[idx] + sig * tanhf(b);
}

// ================= TF32 tensor-core GEMM =================
// C[M,N] = epi(A[M,K] @ W[N,K]^T); block tile 128x64, BK=32,
// 8 warps (4x2), warp tile 32x32 of m16n8k8 tf32 mma.sync.

__device__ __forceinline__ uint32_t cvt_tf32(float f) {
    uint32_t u;
    asm("cvt.rna.tf32.f32 %0, %1;" : "=r"(u) : "f"(f));
    return u;
}

__device__ __forceinline__ void mma_tf32(float* c, const uint32_t* a, const uint32_t* b) {
    asm volatile(
        "mma.sync.aligned.m16n8k8.row.col.f32.tf32.tf32.f32 "
        "{%0,%1,%2,%3}, {%4,%5,%6,%7}, {%8,%9}, {%0,%1,%2,%3};"
        : "+f"(c[0]), "+f"(c[1]), "+f"(c[2]), "+f"(c[3])
        : "r"(a[0]), "r"(a[1]), "r"(a[2]), "r"(a[3]), "r"(b[0]), "r"(b[1]));
}

__global__ __launch_bounds__(256) void gemm_tf32_k(
        const float* __restrict__ A, const float* __restrict__ W,
        const float* __restrict__ bias,
        const float* __restrict__ add0, const float* __restrict__ add1,
        float* __restrict__ C, int N, int Kd, int act) {
    __shared__ uint32_t As[32][132];   // [k][m], pitch 132 (== 4 mod 32)
    __shared__ uint32_t Bs[32][68];    // [k][n], pitch 68  (== 4 mod 32)

    int tid  = threadIdx.x;
    int m0   = blockIdx.y * 128;
    int n0   = blockIdx.x * 64;
    int lane = tid & 31, warp = tid >> 5;
    int gid  = lane >> 2, tig = lane & 3;
    int wm   = (warp >> 1) * 32;       // 4 warps along M
    int wn   = (warp & 1) * 32;        // 2 warps along N

    float acc[2][4][4];
#pragma unroll
    for (int i = 0; i < 2; i++)
#pragma unroll
        for (int j = 0; j < 4; j++)
#pragma unroll
            for (int r = 0; r < 4; r++) acc[i][j][r] = 0.f;

    // gmem fetch assignment
    int am  = tid & 127, akq = tid >> 7;   // A: row am, half akq (k: akq*16 + u*4)
    int bn  = tid & 63,  bkq = tid >> 6;   // B: row bn, quarter bkq (k: bkq*8 + u*4)
    const float* Aptr = A + (size_t)(m0 + am) * Kd + akq * 16;
    const float* Wptr = W + (size_t)(n0 + bn) * Kd + bkq * 8;
    bool bvalid = (n0 + bn) < N;

    float4 ra[4], rb[2];
#pragma unroll
    for (int u = 0; u < 4; u++) ra[u] = ((const float4*)Aptr)[u];
#pragma unroll
    for (int u = 0; u < 2; u++)
        rb[u] = bvalid ? ((const float4*)Wptr)[u] : make_float4(0.f, 0.f, 0.f, 0.f);

    for (int kk = 0; kk < Kd; kk += 32) {
        // store current tile (with tf32 rounding)
#pragma unroll
        for (int u = 0; u < 4; u++) {
            int kr = akq * 16 + u * 4;
            As[kr + 0][am] = cvt_tf32(ra[u].x);
            As[kr + 1][am] = cvt_tf32(ra[u].y);
            As[kr + 2][am] = cvt_tf32(ra[u].z);
            As[kr + 3][am] = cvt_tf32(ra[u].w);
        }
#pragma unroll
        for (int u = 0; u < 2; u++) {
            int kr = bkq * 8 + u * 4;
            Bs[kr + 0][bn] = cvt_tf32(rb[u].x);
            Bs[kr + 1][bn] = cvt_tf32(rb[u].y);
            Bs[kr + 2][bn] = cvt_tf32(rb[u].z);
            Bs[kr + 3][bn] = cvt_tf32(rb[u].w);
        }
        __syncthreads();

        // prefetch next tile into registers
        if (kk + 32 < Kd) {
            Aptr += 32; Wptr += 32;
#pragma unroll
            for (int u = 0; u < 4; u++) ra[u] = ((const float4*)Aptr)[u];
#pragma unroll
            for (int u = 0; u < 2; u++)
                rb[u] = bvalid ? ((const float4*)Wptr)[u] : make_float4(0.f, 0.f, 0.f, 0.f);
        }

        // compute 4 k-steps of 8
#pragma unroll
        for (int ks = 0; ks < 4; ks++) {
            int k0 = ks * 8;
            uint32_t af[2][4], bf[4][2];
#pragma unroll
            for (int i = 0; i < 2; i++) {
                int mi = wm + i * 16 + gid;
                af[i][0] = As[k0 + tig][mi];
                af[i][1] = As[k0 + tig][mi + 8];
                af[i][2] = As[k0 + tig + 4][mi];
                af[i][3] = As[k0 + tig + 4][mi + 8];
            }
#pragma unroll
            for (int j = 0; j < 4; j++) {
                int nj = wn + j * 8 + gid;
                bf[j][0] = Bs[k0 + tig][nj];
                bf[j][1] = Bs[k0 + tig + 4][nj];
            }
#pragma unroll
            for (int i = 0; i < 2; i++)
#pragma unroll
                for (int j = 0; j < 4; j++)
                    mma_tf32(acc[i][j], af[i], bf[j]);
        }
        __syncthreads();
    }

    // epilogue
#pragma unroll
    for (int i = 0; i < 2; i++) {
#pragma unroll
        for (int j = 0; j < 4; j++) {
#pragma unroll
            for (int r = 0; r < 4; r++) {
                int m = m0 + wm + i * 16 + gid + ((r >= 2) ? 8 : 0);
                int n = n0 + wn + j * 8 + tig * 2 + (r & 1);
                if (n < N) {
                    float v = acc[i][j][r];
                    if (bias) v += bias[n];
                    if (act)  v = 0.5f * v * (1.f + erff(v * 0.70710678118654752f));
                    size_t o = (size_t)m * N + n;
                    if (add0) v += add0[o];
                    if (add1) v += add1[o];
                    C[o] = v;
                }
            }
        }
    }
}

// ---------------- host launcher ----------------
extern "C" void kernel_launch(void* const* d_in, const int* in_sizes, int n_in,
                              void* d_out, int out_size) {
    const int*   tokens  = (const int*)  d_in[0];
    const float* emb     = (const float*)d_in[1];
    const float* norm_w  = (const float*)d_in[2];
    const float* dconv_w = (const float*)d_in[3];
    const float* dconv_b = (const float*)d_in[4];
    const float* pconv_w = (const float*)d_in[5];
    const float* pconv_b = (const float*)d_in[6];
    const float* alpha   = (const float*)d_in[7];
    const float* beta    = (const float*)d_in[8];
    const float* w1      = (const float*)d_in[9];
    const float* b1      = (const float*)d_in[10];
    const float* w2      = (const float*)d_in[11];
    const float* b2      = (const float*)d_in[12];
    const float* down_w  = (const float*)d_in[13];
    const float* down_b  = (const float*)d_in[14];
    const float* up_w    = (const float*)d_in[15];
    const float* up_b    = (const float*)d_in[16];
    const float* fnw     = (const float*)d_in[17];
    float* out = (float*)d_out;

    float *px, *pxn, *pcv, *pmid, *pg1, *pg2, *px2, *pxr, *ph;
    cudaGetSymbolAddress((void**)&px,   g_x);
    cudaGetSymbolAddress((void**)&pxn,  g_xn);
    cudaGetSymbolAddress((void**)&pcv,  g_cv);
    cudaGetSymbolAddress((void**)&pmid, g_mid);
    cudaGetSymbolAddress((void**)&pg1,  g_g1);
    cudaGetSymbolAddress((void**)&pg2,  g_g2);
    cudaGetSymbolAddress((void**)&px2,  g_x2);
    cudaGetSymbolAddress((void**)&pxr,  g_xr);
    cudaGetSymbolAddress((void**)&ph,   g_h);

    const int EW_BLOCKS = (Mc * Dc) / 256;
    dim3 gD(Dc / 64, Mc / 128);        // N=512 GEMMs
    dim3 gH(Hc / 64, Mc / 128);        // N=128 GEMM (down)
    dim3 gV((Vc + 63) / 64, Mc / 128); // logits

    embed_rope_k<<<Mc, 256>>>(tokens, emb, px);

    for (int i = 0; i < NLc; i++) {
        int dil = 1 << (i % 3);
        rmsnorm_k<<<Mc, 256>>>(px, norm_w + i * Dc, pxn);
        dconv_k<<<EW_BLOCKS, 256>>>(pxn, dconv_w + (size_t)i * Dc * Kc,
                                    dconv_b + i * Dc, pcv, dil);
        gemm_tf32_k<<<gD, 256>>>(pcv, pconv_w + (size_t)i * Dc * Dc,
                                 pconv_b + i * Dc, nullptr, nullptr, pmid, Dc, Dc, 0);
        recur_k<<<32, 256>>>(pxn, alpha + i * Ac, beta + i * Ac, pxr);
        combine_k<<<EW_BLOCKS, 256>>>(pxn, pxr, pmid);
        gemm_tf32_k<<<gD, 256>>>(pmid, w1 + (size_t)i * Dc * Dc, b1 + i * Dc,
                                 nullptr, nullptr, pg1, Dc, Dc, 0);
        gemm_tf32_k<<<gD, 256>>>(pmid, w2 + (size_t)i * Dc * Dc, b2 + i * Dc,
                                 nullptr, nullptr, pg2, Dc, Dc, 0);
        gate_k<<<EW_BLOCKS, 256>>>(pmid, pg1, pg2, px2);
        gemm_tf32_k<<<gH, 256>>>(px2, down_w + (size_t)i * Hc * Dc, down_b + i * Hc,
                                 nullptr, nullptr, ph, Hc, Dc, 1);
        gemm_tf32_k<<<gD, 256>>>(ph, up_w + (size_t)i * Dc * Hc, up_b + i * Dc,
                                 px2, px, px, Dc, Hc, 0);
    }

    rmsnorm_k<<<Mc, 256>>>(px, fnw, pxn);
    gemm_tf32_k<<<gV, 256>>>(pxn, emb, nullptr, nullptr, nullptr, out, Vc, Dc, 0);
}